// round 2
// baseline (speedup 1.0000x reference)
#include <cuda_runtime.h>
#include <cstdint>

#define T_STEPS 256
#define ISZ 7
#define HSZ 50
#define G4  200            // 4*H
#define EPB 32             // batch elements per block
#define EPT 4              // elements per thread
#define NTHREADS 512

// shared layout (floats)
//  wx0  [7][200]    : 1400   off 0
//  wh0  [50][200]   : 10000  off 1400
//  wi1  [50][200]   : 10000  off 11400
//  wh1  [50][200]   : 10000  off 21400
//  b0   [200]       : 200    off 31400
//  b1   [200]       : 200    off 31600
//  wfc  [7][50]+pad : 352    off 31800
//  bfc  [8]         : 8      off 32152
//  xs   [32][7]     : 224    off 32160
//  h0s  [2][32][50] : 3200   off 32384
//  h1s  [2][32][50] : 3200   off 35584
// total 38784 floats = 155136 bytes
#define SMEM_FLOATS 38784

__device__ __forceinline__ float sigm(float v) {
    return __fdividef(1.f, 1.f + __expf(-v));
}
__device__ __forceinline__ float tanh_f(float v) {
    return __fdividef(2.f, 1.f + __expf(-2.f * v)) - 1.f;
}

__global__ __launch_bounds__(NTHREADS, 1)
void lstm2_fused_kernel(const float* __restrict__ x,
                        const float* __restrict__ w_ih0, const float* __restrict__ w_hh0,
                        const float* __restrict__ b_ih0, const float* __restrict__ b_hh0,
                        const float* __restrict__ w_ih1, const float* __restrict__ w_hh1,
                        const float* __restrict__ b_ih1, const float* __restrict__ b_hh1,
                        const float* __restrict__ w_fc,  const float* __restrict__ b_fc,
                        float* __restrict__ out)
{
    extern __shared__ float sm[];
    float* wx0 = sm;                 // [k][200]
    float* wh0 = sm + 1400;
    float* wi1 = sm + 11400;
    float* wh1 = sm + 21400;
    float* b0  = sm + 31400;
    float* b1  = sm + 31600;
    float* wfc = sm + 31800;
    float* bfc = sm + 32152;
    float* xs  = sm + 32160;         // [32][7]
    float* h0s = sm + 32384;         // [2][32][50]
    float* h1s = sm + 35584;         // [2][32][50]

    const int tid = threadIdx.x;

    // ---- load weights into shared, transposed to [k][gate] ----
    for (int i = tid; i < G4 * ISZ; i += NTHREADS) {
        int g = i / ISZ, k = i % ISZ;
        wx0[k * G4 + g] = w_ih0[i];
    }
    for (int i = tid; i < G4 * HSZ; i += NTHREADS) {
        int g = i / HSZ, k = i % HSZ;
        float v0 = w_hh0[i], v1 = w_ih1[i], v2 = w_hh1[i];
        wh0[k * G4 + g] = v0;
        wi1[k * G4 + g] = v1;
        wh1[k * G4 + g] = v2;
    }
    for (int i = tid; i < G4; i += NTHREADS) {
        b0[i] = b_ih0[i] + b_hh0[i];
        b1[i] = b_ih1[i] + b_hh1[i];
    }
    for (int i = tid; i < ISZ * HSZ; i += NTHREADS) wfc[i] = w_fc[i];
    if (tid < ISZ) bfc[tid] = b_fc[tid];
    // zero both state buffers
    for (int i = tid; i < 2 * EPB * HSZ; i += NTHREADS) { h0s[i] = 0.f; h1s[i] = 0.f; }
    __syncthreads();

    const int j   = tid & 63;        // cell slot
    const int grp = tid >> 6;        // element group (0..7)
    const int leb = grp * EPT;       // local element base
    const bool act = (j < HSZ);

    float bi0 = 0.f, bf0 = 0.f, bg0 = 0.f, bo0 = 0.f;
    float bi1 = 0.f, bf1 = 0.f, bg1 = 0.f, bo1 = 0.f;
    if (act) {
        bi0 = b0[j]; bf0 = b0[50 + j]; bg0 = b0[100 + j]; bo0 = b0[150 + j];
        bi1 = b1[j]; bf1 = b1[50 + j]; bg1 = b1[100 + j]; bo1 = b1[150 + j];
    }

    float c0[EPT] = {0.f, 0.f, 0.f, 0.f};
    float c1[EPT] = {0.f, 0.f, 0.f, 0.f};

    // x loader mapping: tid < 224 -> (local element, feature)
    const int xle = tid / ISZ;
    const int xk  = tid % ISZ;
    const float* xptr = x;
    if (tid < EPB * ISZ)
        xptr = x + (size_t)(blockIdx.x * EPB + xle) * (T_STEPS * ISZ) + xk;

    int buf = 0;
    for (int t = 0; t < T_STEPS; ++t) {
        // issue x load early; lands during recurrent compute
        float xv = 0.f;
        if (tid < EPB * ISZ) xv = xptr[t * ISZ];

        float A[EPT], F[EPT], Gv[EPT], O[EPT];

        // ---- layer0: recurrent part ----
        if (act) {
            #pragma unroll
            for (int e = 0; e < EPT; e++) { A[e] = bi0; F[e] = bf0; Gv[e] = bg0; O[e] = bo0; }
            const float* hb = h0s + buf * (EPB * HSZ) + leb * HSZ;
            #pragma unroll 10
            for (int k = 0; k < HSZ; k++) {
                const float wi_ = wh0[k * G4 + j];
                const float wf_ = wh0[k * G4 + 50 + j];
                const float wg_ = wh0[k * G4 + 100 + j];
                const float wo_ = wh0[k * G4 + 150 + j];
                #pragma unroll
                for (int e = 0; e < EPT; e++) {
                    const float hk = hb[e * HSZ + k];
                    A[e]  = fmaf(wi_, hk, A[e]);
                    F[e]  = fmaf(wf_, hk, F[e]);
                    Gv[e] = fmaf(wg_, hk, Gv[e]);
                    O[e]  = fmaf(wo_, hk, O[e]);
                }
            }
        }
        if (tid < EPB * ISZ) xs[tid] = xv;
        __syncthreads();   // S1: x_t visible

        if (act) {
            // ---- layer0: input part + activations ----
            #pragma unroll
            for (int k = 0; k < ISZ; k++) {
                const float wi_ = wx0[k * G4 + j];
                const float wf_ = wx0[k * G4 + 50 + j];
                const float wg_ = wx0[k * G4 + 100 + j];
                const float wo_ = wx0[k * G4 + 150 + j];
                #pragma unroll
                for (int e = 0; e < EPT; e++) {
                    const float xk_ = xs[(leb + e) * ISZ + k];
                    A[e]  = fmaf(wi_, xk_, A[e]);
                    F[e]  = fmaf(wf_, xk_, F[e]);
                    Gv[e] = fmaf(wg_, xk_, Gv[e]);
                    O[e]  = fmaf(wo_, xk_, O[e]);
                }
            }
            float* hnb = h0s + (buf ^ 1) * (EPB * HSZ) + leb * HSZ;
            #pragma unroll
            for (int e = 0; e < EPT; e++) {
                const float ig = sigm(A[e]);
                const float fg = sigm(F[e]);
                const float gg = tanh_f(Gv[e]);
                const float og = sigm(O[e]);
                c0[e] = fmaf(fg, c0[e], ig * gg);
                hnb[e * HSZ + j] = og * tanh_f(c0[e]);
            }
        }
        __syncthreads();   // S2: new h0 visible

        // ---- layer1 ----
        if (act) {
            #pragma unroll
            for (int e = 0; e < EPT; e++) { A[e] = bi1; F[e] = bf1; Gv[e] = bg1; O[e] = bo1; }
            const float* h0n = h0s + (buf ^ 1) * (EPB * HSZ) + leb * HSZ;
            #pragma unroll 10
            for (int k = 0; k < HSZ; k++) {
                const float wi_ = wi1[k * G4 + j];
                const float wf_ = wi1[k * G4 + 50 + j];
                const float wg_ = wi1[k * G4 + 100 + j];
                const float wo_ = wi1[k * G4 + 150 + j];
                #pragma unroll
                for (int e = 0; e < EPT; e++) {
                    const float hk = h0n[e * HSZ + k];
                    A[e]  = fmaf(wi_, hk, A[e]);
                    F[e]  = fmaf(wf_, hk, F[e]);
                    Gv[e] = fmaf(wg_, hk, Gv[e]);
                    O[e]  = fmaf(wo_, hk, O[e]);
                }
            }
            const float* h1b = h1s + buf * (EPB * HSZ) + leb * HSZ;
            #pragma unroll 10
            for (int k = 0; k < HSZ; k++) {
                const float wi_ = wh1[k * G4 + j];
                const float wf_ = wh1[k * G4 + 50 + j];
                const float wg_ = wh1[k * G4 + 100 + j];
                const float wo_ = wh1[k * G4 + 150 + j];
                #pragma unroll
                for (int e = 0; e < EPT; e++) {
                    const float hk = h1b[e * HSZ + k];
                    A[e]  = fmaf(wi_, hk, A[e]);
                    F[e]  = fmaf(wf_, hk, F[e]);
                    Gv[e] = fmaf(wg_, hk, Gv[e]);
                    O[e]  = fmaf(wo_, hk, O[e]);
                }
            }
            float* h1n = h1s + (buf ^ 1) * (EPB * HSZ) + leb * HSZ;
            #pragma unroll
            for (int e = 0; e < EPT; e++) {
                const float ig = sigm(A[e]);
                const float fg = sigm(F[e]);
                const float gg = tanh_f(Gv[e]);
                const float og = sigm(O[e]);
                c1[e] = fmaf(fg, c1[e], ig * gg);
                h1n[e * HSZ + j] = og * tanh_f(c1[e]);
            }
        }
        __syncthreads();   // S3: new h1 visible
        buf ^= 1;
    }

    // ---- FC head: out[e][i] = b_fc[i] + sum_j w_fc[i][j] * h2[e][j] ----
    if (j < ISZ) {
        const float* h2 = h1s + buf * (EPB * HSZ) + leb * HSZ;
        #pragma unroll
        for (int e = 0; e < EPT; e++) {
            float s = bfc[j];
            #pragma unroll 10
            for (int k = 0; k < HSZ; k++)
                s = fmaf(wfc[j * HSZ + k], h2[e * HSZ + k], s);
            out[(size_t)(blockIdx.x * EPB + leb + e) * ISZ + j] = s;
        }
    }
}

extern "C" void kernel_launch(void* const* d_in, const int* in_sizes, int n_in,
                              void* d_out, int out_size)
{
    const float* x     = (const float*)d_in[0];
    const float* w_ih0 = (const float*)d_in[1];
    const float* w_hh0 = (const float*)d_in[2];
    const float* b_ih0 = (const float*)d_in[3];
    const float* b_hh0 = (const float*)d_in[4];
    const float* w_ih1 = (const float*)d_in[5];
    const float* w_hh1 = (const float*)d_in[6];
    const float* b_ih1 = (const float*)d_in[7];
    const float* b_hh1 = (const float*)d_in[8];
    const float* w_fc  = (const float*)d_in[9];
    const float* b_fc  = (const float*)d_in[10];
    float* out = (float*)d_out;

    const size_t smem_bytes = SMEM_FLOATS * sizeof(float);
    cudaFuncSetAttribute(lstm2_fused_kernel,
                         cudaFuncAttributeMaxDynamicSharedMemorySize,
                         (int)smem_bytes);

    lstm2_fused_kernel<<<4096 / EPB, NTHREADS, smem_bytes>>>(
        x, w_ih0, w_hh0, b_ih0, b_hh0,
        w_ih1, w_hh1, b_ih1, b_hh1,
        w_fc, b_fc, out);
}

// round 4
// speedup vs baseline: 1.3571x; 1.3571x over previous
#include <cuda_runtime.h>
#include <cstdint>

#define TSTEPS 256
#define HSZ 50
#define ISZ 7
#define EPB 32
#define NTHREADS 256
#define NBLOCKS 128

typedef unsigned long long u64;

// smem layout (float offsets)
#define OFF_WX0 0        // [7][50][4]   1400
#define OFF_WH0 1400     // [50][50][4] 10000
#define OFF_WI1 11400    // [50][50][4] 10000
#define OFF_WH1 21400    // [50][50][4] 10000
#define OFF_B0  31400    // [50][4]       200
#define OFF_B1  31600    // [50][4]       200
#define OFF_WFC 31800    // [7][50]       350
#define OFF_BFC 32152    // [8]             8
#define OFF_XS  32160    // [2][7][32]    448
#define OFF_H0  32608    // [2][50][32]  3200
#define OFF_H1  35808    // [2][50][32]  3200
#define SMEM_FLOATS 39008

__device__ __forceinline__ u64 pk2(float lo, float hi) {
    u64 r; asm("mov.b64 %0,{%1,%2};" : "=l"(r) : "f"(lo), "f"(hi)); return r;
}
__device__ __forceinline__ void upk2(float& lo, float& hi, u64 v) {
    asm("mov.b64 {%0,%1},%2;" : "=f"(lo), "=f"(hi) : "l"(v));
}
__device__ __forceinline__ void fma2(u64& c, u64 a, u64 b) {
    asm("fma.rn.f32x2 %0,%1,%2,%0;" : "+l"(c) : "l"(a), "l"(b));
}

__device__ __forceinline__ float sigm(float v) {
    return __fdividef(1.f, 1.f + __expf(-v));
}
__device__ __forceinline__ float tanh_f(float v) {
    return __fdividef(2.f, 1.f + __expf(-2.f * v)) - 1.f;
}

// 50-step matvec accumulate. Wp: packed weights [(k*50+j)*4 + gate].
// hb: h base already offset by this thread's g*8 (row stride 32 floats).
// acc[gate*4 + p], pair p covers elements 2p, 2p+1.
__device__ __forceinline__ void mv50(const float* __restrict__ Wp,
                                     const float* __restrict__ hb,
                                     int j, u64 acc[16]) {
    #pragma unroll 10
    for (int k = 0; k < HSZ; k++) {
        const float4 w4 = *reinterpret_cast<const float4*>(Wp + (k * HSZ + j) * 4);
        const u64 wi = pk2(w4.x, w4.x), wf = pk2(w4.y, w4.y);
        const u64 wg = pk2(w4.z, w4.z), wo = pk2(w4.w, w4.w);
        const ulonglong2 ha = *reinterpret_cast<const ulonglong2*>(hb + k * EPB);
        const ulonglong2 hc = *reinterpret_cast<const ulonglong2*>(hb + k * EPB + 4);
        fma2(acc[0],  wi, ha.x); fma2(acc[1],  wi, ha.y); fma2(acc[2],  wi, hc.x); fma2(acc[3],  wi, hc.y);
        fma2(acc[4],  wf, ha.x); fma2(acc[5],  wf, ha.y); fma2(acc[6],  wf, hc.x); fma2(acc[7],  wf, hc.y);
        fma2(acc[8],  wg, ha.x); fma2(acc[9],  wg, ha.y); fma2(acc[10], wg, hc.x); fma2(acc[11], wg, hc.y);
        fma2(acc[12], wo, ha.x); fma2(acc[13], wo, ha.y); fma2(acc[14], wo, hc.x); fma2(acc[15], wo, hc.y);
    }
}

__device__ __forceinline__ void mv7(const float* __restrict__ Wp,
                                    const float* __restrict__ xb,
                                    int j, u64 acc[16]) {
    #pragma unroll
    for (int k = 0; k < ISZ; k++) {
        const float4 w4 = *reinterpret_cast<const float4*>(Wp + (k * HSZ + j) * 4);
        const u64 wi = pk2(w4.x, w4.x), wf = pk2(w4.y, w4.y);
        const u64 wg = pk2(w4.z, w4.z), wo = pk2(w4.w, w4.w);
        const ulonglong2 ha = *reinterpret_cast<const ulonglong2*>(xb + k * EPB);
        const ulonglong2 hc = *reinterpret_cast<const ulonglong2*>(xb + k * EPB + 4);
        fma2(acc[0],  wi, ha.x); fma2(acc[1],  wi, ha.y); fma2(acc[2],  wi, hc.x); fma2(acc[3],  wi, hc.y);
        fma2(acc[4],  wf, ha.x); fma2(acc[5],  wf, ha.y); fma2(acc[6],  wf, hc.x); fma2(acc[7],  wf, hc.y);
        fma2(acc[8],  wg, ha.x); fma2(acc[9],  wg, ha.y); fma2(acc[10], wg, hc.x); fma2(acc[11], wg, hc.y);
        fma2(acc[12], wo, ha.x); fma2(acc[13], wo, ha.y); fma2(acc[14], wo, hc.x); fma2(acc[15], wo, hc.y);
    }
}

__device__ __forceinline__ void gates(const u64 acc[16], float c[8], float hn[8]) {
    #pragma unroll
    for (int p = 0; p < 4; p++) {
        float i0, i1, f0, f1, g0, g1, o0, o1;
        upk2(i0, i1, acc[p]);
        upk2(f0, f1, acc[4 + p]);
        upk2(g0, g1, acc[8 + p]);
        upk2(o0, o1, acc[12 + p]);
        const int e = 2 * p;
        c[e]     = sigm(f0) * c[e]     + sigm(i0) * tanh_f(g0);
        c[e + 1] = sigm(f1) * c[e + 1] + sigm(i1) * tanh_f(g1);
        hn[e]     = sigm(o0) * tanh_f(c[e]);
        hn[e + 1] = sigm(o1) * tanh_f(c[e + 1]);
    }
}

__global__ __launch_bounds__(NTHREADS, 1)
void lstm2_fused_v2(const float* __restrict__ x,
                    const float* __restrict__ w_ih0, const float* __restrict__ w_hh0,
                    const float* __restrict__ b_ih0, const float* __restrict__ b_hh0,
                    const float* __restrict__ w_ih1, const float* __restrict__ w_hh1,
                    const float* __restrict__ b_ih1, const float* __restrict__ b_hh1,
                    const float* __restrict__ w_fc,  const float* __restrict__ b_fc,
                    float* __restrict__ out)
{
    extern __shared__ float sm[];
    const int tid = threadIdx.x;
    const int blk = blockIdx.x;

    // ---- stage weights to shared, packed/transposed ----
    for (int i = tid; i < HSZ * HSZ * 4; i += NTHREADS) {       // 10000 each
        const int k = i / 200, r = i % 200;
        const int j = r >> 2, gi = r & 3;
        const int src = (gi * HSZ + j) * HSZ + k;
        sm[OFF_WH0 + i] = w_hh0[src];
        sm[OFF_WI1 + i] = w_ih1[src];
        sm[OFF_WH1 + i] = w_hh1[src];
    }
    for (int i = tid; i < ISZ * HSZ * 4; i += NTHREADS) {       // 1400
        const int k = i / 200, r = i % 200;
        const int j = r >> 2, gi = r & 3;
        sm[OFF_WX0 + i] = w_ih0[(gi * HSZ + j) * ISZ + k];
    }
    for (int i = tid; i < 200; i += NTHREADS) {
        const int j = i >> 2, gi = i & 3;
        sm[OFF_B0 + i] = b_ih0[gi * HSZ + j] + b_hh0[gi * HSZ + j];
        sm[OFF_B1 + i] = b_ih1[gi * HSZ + j] + b_hh1[gi * HSZ + j];
    }
    for (int i = tid; i < ISZ * HSZ; i += NTHREADS) sm[OFF_WFC + i] = w_fc[i];
    if (tid < ISZ) sm[OFF_BFC + tid] = b_fc[tid];
    // zero both h buffers
    for (int i = tid; i < 2 * HSZ * EPB; i += NTHREADS) {
        sm[OFF_H0 + i] = 0.f;
        sm[OFF_H1 + i] = 0.f;
    }
    // preload x for t=0 into xs buffer 0: xs[k][e]
    for (int i = tid; i < ISZ * EPB; i += NTHREADS) {
        const int e = i & 31, kx = i >> 5;
        sm[OFF_XS + kx * 32 + e] = x[(size_t)(blk * EPB + e) * (TSTEPS * ISZ) + kx];
    }
    __syncthreads();

    const int j = tid >> 2;          // cell 0..63 (active < 50)
    const int g = tid & 3;           // element group, 8 elems each
    const bool act = (j < HSZ);
    const int go = g * 8;            // element offset within block

    float4 b0v = make_float4(0.f, 0.f, 0.f, 0.f), b1v = b0v;
    if (act) {
        b0v = *reinterpret_cast<const float4*>(sm + OFF_B0 + j * 4);
        b1v = *reinterpret_cast<const float4*>(sm + OFF_B1 + j * 4);
    }

    // per-step x loader: tid<224, kx = tid>>5, e = tid&31
    const float* xp = x;
    if (tid < EPB * ISZ)
        xp = x + (size_t)(blk * EPB + (tid & 31)) * (TSTEPS * ISZ) + (tid >> 5);

    float c0[8] = {0.f, 0.f, 0.f, 0.f, 0.f, 0.f, 0.f, 0.f};
    float c1[8] = {0.f, 0.f, 0.f, 0.f, 0.f, 0.f, 0.f, 0.f};
    u64 acc[16];

    int buf = 0;
    for (int t = 0; t < TSTEPS; t++) {
        // prefetch x_{t+1} (lands during compute)
        float xv = 0.f;
        if (tid < EPB * ISZ && t + 1 < TSTEPS) xv = xp[(t + 1) * ISZ];

        // ---- layer 0 ----
        if (act) {
            #pragma unroll
            for (int p = 0; p < 4; p++) {
                acc[p]      = pk2(b0v.x, b0v.x);
                acc[4 + p]  = pk2(b0v.y, b0v.y);
                acc[8 + p]  = pk2(b0v.z, b0v.z);
                acc[12 + p] = pk2(b0v.w, b0v.w);
            }
            mv50(sm + OFF_WH0, sm + OFF_H0 + buf * 1600 + go, j, acc);
            mv7 (sm + OFF_WX0, sm + OFF_XS + buf * 224  + go, j, acc);
            float hn[8];
            gates(acc, c0, hn);
            float* hd = sm + OFF_H0 + (buf ^ 1) * 1600 + j * EPB + go;
            *reinterpret_cast<float4*>(hd)     = make_float4(hn[0], hn[1], hn[2], hn[3]);
            *reinterpret_cast<float4*>(hd + 4) = make_float4(hn[4], hn[5], hn[6], hn[7]);
        }
        __syncthreads();   // A: new h0 visible

        // ---- layer 1 ----
        if (act) {
            #pragma unroll
            for (int p = 0; p < 4; p++) {
                acc[p]      = pk2(b1v.x, b1v.x);
                acc[4 + p]  = pk2(b1v.y, b1v.y);
                acc[8 + p]  = pk2(b1v.z, b1v.z);
                acc[12 + p] = pk2(b1v.w, b1v.w);
            }
            mv50(sm + OFF_WI1, sm + OFF_H0 + (buf ^ 1) * 1600 + go, j, acc);
            mv50(sm + OFF_WH1, sm + OFF_H1 + buf * 1600 + go, j, acc);
            float hn[8];
            gates(acc, c1, hn);
            float* hd = sm + OFF_H1 + (buf ^ 1) * 1600 + j * EPB + go;
            *reinterpret_cast<float4*>(hd)     = make_float4(hn[0], hn[1], hn[2], hn[3]);
            *reinterpret_cast<float4*>(hd + 4) = make_float4(hn[4], hn[5], hn[6], hn[7]);
        }
        if (tid < EPB * ISZ) sm[OFF_XS + (buf ^ 1) * 224 + tid] = xv;
        __syncthreads();   // B: new h1 + new x visible
        buf ^= 1;
    }

    // ---- FC head ----
    if (j < ISZ) {
        const float* h2 = sm + OFF_H1 + buf * 1600 + go;
        float s[8];
        const float bv = sm[OFF_BFC + j];
        #pragma unroll
        for (int e = 0; e < 8; e++) s[e] = bv;
        #pragma unroll 10
        for (int k = 0; k < HSZ; k++) {
            const float wv = sm[OFF_WFC + j * HSZ + k];
            #pragma unroll
            for (int e = 0; e < 8; e++) s[e] = fmaf(wv, h2[k * EPB + e], s[e]);
        }
        #pragma unroll
        for (int e = 0; e < 8; e++)
            out[(size_t)(blk * EPB + go + e) * ISZ + j] = s[e];
    }
}

extern "C" void kernel_launch(void* const* d_in, const int* in_sizes, int n_in,
                              void* d_out, int out_size)
{
    const float* x     = (const float*)d_in[0];
    const float* w_ih0 = (const float*)d_in[1];
    const float* w_hh0 = (const float*)d_in[2];
    const float* b_ih0 = (const float*)d_in[3];
    const float* b_hh0 = (const float*)d_in[4];
    const float* w_ih1 = (const float*)d_in[5];
    const float* w_hh1 = (const float*)d_in[6];
    const float* b_ih1 = (const float*)d_in[7];
    const float* b_hh1 = (const float*)d_in[8];
    const float* w_fc  = (const float*)d_in[9];
    const float* b_fc  = (const float*)d_in[10];
    float* out = (float*)d_out;

    const size_t smem_bytes = SMEM_FLOATS * sizeof(float);
    cudaFuncSetAttribute(lstm2_fused_v2,
                         cudaFuncAttributeMaxDynamicSharedMemorySize,
                         (int)smem_bytes);

    lstm2_fused_v2<<<NBLOCKS, NTHREADS, smem_bytes>>>(
        x, w_ih0, w_hh0, b_ih0, b_hh0,
        w_ih1, w_hh1, b_ih1, b_hh1,
        w_fc, b_fc, out);
}